// round 12
// baseline (speedup 1.0000x reference)
#include <cuda_runtime.h>
#include <cstdint>
#include <cstddef>

// LISTA-CPSS: B=16384, M=256, N=1024, DEPTH=16
// Exact fp32 SIMT GEMM: 32x64 warp tiles, aligned single-wavefront LDS.128,
// BK=16, double-buffered smem (ONE barrier per chunk), register prefetch.
// + 2-phase bit-exact radix select.

#define B_DIM  16384
#define M_DIM  256
#define N_DIM  1024
#define DEPTH  16

__device__ float g_r[(size_t)B_DIM * M_DIM];
__device__ float g_v[(size_t)B_DIM * N_DIM];
__device__ float g_u[(size_t)B_DIM * N_DIM];

// ---------------------------------------------------------------------------
// Tiled SGEMM: C[i,j] = epilogue( sum_k X[i,k]*Y[j,k] );  X:[I,K], Y:[J,K].
// MODE 0: C = bias - acc ; MODE 1: C = bias + acc ; MODE 2: C = acc
// 128x128 CTA tile, BK=16, 256 threads, warp tile 32x64, lane tile 8x8
// (2+2 float4 spans -> every LDS.128 is one aligned conflict-free wavefront).
// Double-buffered smem: iteration ch = {sync; LDG ch+1 -> regs; FMA from
// buf[ch&1]; STS regs -> buf[(ch+1)&1]}. Stores target the buffer whose
// readers finished at this iteration's barrier -> race-free with 1 sync.
// Per-element k-order identical to R2/R10/R11 kernels (bit-exact result).
// ---------------------------------------------------------------------------
template <int MODE>
__global__ void __launch_bounds__(256, 2)
gemm_nt(const float* __restrict__ X, const float* __restrict__ Y,
        const float* __restrict__ bias, float* __restrict__ C,
        int K, int ldc)
{
    __shared__ float sX[2][16][128];
    __shared__ float sY[2][16][128];

    const int bi  = blockIdx.x;
    const int bj  = blockIdx.y;
    const int tid = threadIdx.x;

    // ---- global -> smem loader mapping ----
    const int loadRow = tid >> 1;          // 0..127
    const int kBase   = (tid & 1) * 8;     // 0 or 8

    const float* xg = X + (size_t)(bi * 128 + loadRow) * K + kBase;
    const float* yg = Y + (size_t)(bj * 128 + loadRow) * K + kBase;

    // ---- compute mapping: warp tile 32x64, lane tile 8x8 ----
    const int lane = tid & 31;
    const int warp = tid >> 5;
    const int wy = warp & 3;
    const int wx = warp >> 2;
    const int ty = lane >> 3;
    const int tx = lane & 7;

    const int r0 = wy * 32 + ty * 4;
    const int r1 = r0 + 16;
    const int c0 = wx * 64 + tx * 4;
    const int c1 = c0 + 32;

    float acc[8][8];
#pragma unroll
    for (int p = 0; p < 8; ++p)
#pragma unroll
        for (int q = 0; q < 8; ++q) acc[p][q] = 0.0f;

    const int nch = K >> 4;   // chunks of 16

    // prologue: load chunk 0 and stage into buffer 0 (no barrier needed yet)
    float4 xv0 = *reinterpret_cast<const float4*>(xg);
    float4 xv1 = *reinterpret_cast<const float4*>(xg + 4);
    float4 yv0 = *reinterpret_cast<const float4*>(yg);
    float4 yv1 = *reinterpret_cast<const float4*>(yg + 4);
    {
        const float xa[8] = {xv0.x, xv0.y, xv0.z, xv0.w, xv1.x, xv1.y, xv1.z, xv1.w};
        const float ya[8] = {yv0.x, yv0.y, yv0.z, yv0.w, yv1.x, yv1.y, yv1.z, yv1.w};
#pragma unroll
        for (int i = 0; i < 8; ++i) {
            sX[0][kBase + i][loadRow] = xa[i];
            sY[0][kBase + i][loadRow] = ya[i];
        }
    }

#pragma unroll 1
    for (int ch = 0; ch < nch; ++ch) {
        __syncthreads();   // buf[ch&1] fully staged; buf[(ch+1)&1] fully drained

        const bool more = (ch + 1 < nch);
        if (more) {
            const float* xn = xg + (ch + 1) * 16;
            const float* yn = yg + (ch + 1) * 16;
            xv0 = *reinterpret_cast<const float4*>(xn);
            xv1 = *reinterpret_cast<const float4*>(xn + 4);
            yv0 = *reinterpret_cast<const float4*>(yn);
            yv1 = *reinterpret_cast<const float4*>(yn + 4);
        }

        const int s = ch & 1;
#pragma unroll
        for (int k = 0; k < 16; ++k) {
            const float4 a0 = *reinterpret_cast<const float4*>(&sX[s][k][r0]);
            const float4 a1 = *reinterpret_cast<const float4*>(&sX[s][k][r1]);
            const float4 b0 = *reinterpret_cast<const float4*>(&sY[s][k][c0]);
            const float4 b1 = *reinterpret_cast<const float4*>(&sY[s][k][c1]);
            const float a[8] = {a0.x, a0.y, a0.z, a0.w, a1.x, a1.y, a1.z, a1.w};
            const float b[8] = {b0.x, b0.y, b0.z, b0.w, b1.x, b1.y, b1.z, b1.w};
#pragma unroll
            for (int p = 0; p < 8; ++p)
#pragma unroll
                for (int q = 0; q < 8; ++q) acc[p][q] += a[p] * b[q];
        }

        if (more) {
            const int sn = (ch + 1) & 1;
            const float xa[8] = {xv0.x, xv0.y, xv0.z, xv0.w, xv1.x, xv1.y, xv1.z, xv1.w};
            const float ya[8] = {yv0.x, yv0.y, yv0.z, yv0.w, yv1.x, yv1.y, yv1.z, yv1.w};
#pragma unroll
            for (int i = 0; i < 8; ++i) {
                sX[sn][kBase + i][loadRow] = xa[i];
                sY[sn][kBase + i][loadRow] = ya[i];
            }
        }
    }

    // ---- epilogue ----
    const int gr0 = bi * 128;
    const int gc0 = bj * 128;
#pragma unroll
    for (int p = 0; p < 8; ++p) {
        const int rr = gr0 + ((p < 4) ? (r0 + p) : (r1 + p - 4));
#pragma unroll
        for (int half = 0; half < 2; ++half) {
            const int cc = gc0 + ((half == 0) ? c0 : c1);
            const size_t base = (size_t)rr * ldc + cc;
            float4 o;
            float* po = reinterpret_cast<float*>(&o);
#pragma unroll
            for (int q = 0; q < 4; ++q) {
                float v = acc[p][half * 4 + q];
                if (MODE == 0)      v = bias[base + q] - v;
                else if (MODE == 1) v = bias[base + q] + v;
                po[q] = v;
            }
            *reinterpret_cast<float4*>(C + base) = o;
        }
    }
}

// ---------------------------------------------------------------------------
// select_shrink: bit-exact k-th largest |v| per row, 2-phase:
//   Phase A: 1024-bin histogram over top-11 bits + block suffix-scan.
//   Phase B: boundary-bin candidates, 3 radix passes over the small list.
// Then masked soft-threshold.
// ---------------------------------------------------------------------------
__global__ void __launch_bounds__(256)
select_shrink(const float* __restrict__ V, float* __restrict__ U,
              const float* __restrict__ thr, int iter, int kth)
{
    __shared__ unsigned s_hist[1024];
    __shared__ unsigned s_cand[1024];
    __shared__ unsigned s_wtot[8];
    __shared__ unsigned s_wabove[8];
    __shared__ unsigned s_sel[2];
    __shared__ unsigned s_cnt;

    const int row  = blockIdx.x;
    const int tid  = threadIdx.x;
    const int lane = tid & 31;
    const int wrp  = tid >> 5;

    const float4 vv = reinterpret_cast<const float4*>(V + (size_t)row * N_DIM)[tid];
    float va[4] = {vv.x, vv.y, vv.z, vv.w};
    unsigned key[4];
#pragma unroll
    for (int e = 0; e < 4; ++e) key[e] = __float_as_uint(fabsf(va[e]));

    // ---- Phase A ----
#pragma unroll
    for (int i = 0; i < 4; ++i) s_hist[tid * 4 + i] = 0;
    __syncthreads();
#pragma unroll
    for (int e = 0; e < 4; ++e) atomicAdd(&s_hist[key[e] >> 21], 1u);
    __syncthreads();

    unsigned h[4], ls[4];
#pragma unroll
    for (int i = 0; i < 4; ++i) h[i] = s_hist[tid * 4 + i];
    ls[3] = h[3];
#pragma unroll
    for (int i = 2; i >= 0; --i) ls[i] = h[i] + ls[i + 1];
    const unsigned tot = ls[0];

    unsigned suf = tot;
#pragma unroll
    for (int d = 1; d < 32; d <<= 1) {
        const unsigned t = __shfl_down_sync(0xFFFFFFFFu, suf, d);
        if (lane + d < 32) suf += t;
    }
    if (lane == 0) s_wtot[wrp] = suf;
    __syncthreads();
    if (tid == 0) {
        unsigned run = 0;
        for (int w = 7; w >= 0; --w) { s_wabove[w] = run; run += s_wtot[w]; }
    }
    __syncthreads();

    {
        const unsigned A = s_wabove[wrp] + (suf - tot);
        const unsigned k = (unsigned)kth;
#pragma unroll
        for (int i = 0; i < 4; ++i) {
            const unsigned sb = A + ls[i];
            const unsigned sn = (i < 3) ? (A + ls[i + 1]) : A;
            if (sb >= k && sn < k) {
                s_sel[0] = (unsigned)(tid * 4 + i);
                s_sel[1] = k - sn;
            }
        }
    }
    __syncthreads();
    const unsigned selbin = s_sel[0];
    unsigned rem          = s_sel[1];

    // ---- Phase B ----
    if (tid == 0) s_cnt = 0;
    __syncthreads();
#pragma unroll
    for (int e = 0; e < 4; ++e) {
        if ((key[e] >> 21) == selbin) {
            const unsigned idx = atomicAdd(&s_cnt, 1u);
            s_cand[idx] = key[e];
        }
    }
    __syncthreads();
    const unsigned c = s_cnt;

    unsigned prefix = selbin << 21;
    const int SHIFT[3] = {13, 5, 0};
    const unsigned HIMASK[3] = {0xFFE00000u, 0xFFFFE000u, 0xFFFFFFE0u};
    const unsigned BMASK[3]  = {255u, 255u, 31u};

#pragma unroll 1
    for (int pass = 0; pass < 3; ++pass) {
        if (tid < 256) s_hist[tid] = 0;
        __syncthreads();
        for (unsigned j = tid; j < c; j += 256) {
            const unsigned kk = s_cand[j];
            if ((kk & HIMASK[pass]) == prefix)
                atomicAdd(&s_hist[(kk >> SHIFT[pass]) & BMASK[pass]], 1u);
        }
        __syncthreads();

        if (tid < 32) {
            unsigned v8[8], l8[8];
#pragma unroll
            for (int i = 0; i < 8; ++i) v8[i] = s_hist[tid * 8 + i];
            l8[7] = v8[7];
#pragma unroll
            for (int i = 6; i >= 0; --i) l8[i] = v8[i] + l8[i + 1];
            const unsigned t8 = l8[0];
            unsigned sf = t8;
#pragma unroll
            for (int d = 1; d < 32; d <<= 1) {
                const unsigned t = __shfl_down_sync(0xFFFFFFFFu, sf, d);
                if (tid + d < 32) sf += t;
            }
            const unsigned above = sf - t8;
#pragma unroll
            for (int i = 0; i < 8; ++i) {
                const unsigned sb = above + l8[i];
                const unsigned sn = above + ((i < 7) ? l8[i + 1] : 0u);
                if (sb >= rem && sn < rem) {
                    s_sel[0] = (unsigned)(tid * 8 + i);
                    s_sel[1] = rem - sn;
                }
            }
        }
        __syncthreads();
        prefix |= s_sel[0] << SHIFT[pass];
        rem     = s_sel[1];
        __syncthreads();
    }

    const float th = __uint_as_float(prefix);
    const float t  = thr[iter];

    float4 ov;
    float* po = reinterpret_cast<float*>(&ov);
#pragma unroll
    for (int e = 0; e < 4; ++e) {
        const float x = va[e];
        const float a = fabsf(x);
        po[e] = (a >= t && a >= th) ? x : copysignf(fmaxf(a - t, 0.0f), x);
    }
    reinterpret_cast<float4*>(U + (size_t)row * N_DIM)[tid] = ov;
}

// ---------------------------------------------------------------------------
extern "C" void kernel_launch(void* const* d_in, const int* in_sizes, int n_in,
                              void* d_out, int out_size)
{
    const float* x   = (const float*)d_in[0];   // [B, M]
    const float* A   = (const float*)d_in[1];   // [M, N]
    const float* W   = (const float*)d_in[2];   // [DEPTH, N, M]
    const float* thr = (const float*)d_in[3];   // [DEPTH]
    float* uout = (float*)d_out;                // [B, N]

    float *rp, *vp, *up;
    cudaGetSymbolAddress((void**)&rp, g_r);
    cudaGetSymbolAddress((void**)&vp, g_v);
    cudaGetSymbolAddress((void**)&up, g_u);

    // kth_i = 1024 - (ceil((100 - p_i)/100 * 1024) - 1), p_i = min((i+1)*1.2, 5)
    static const int KTH[DEPTH] = {13, 25, 37, 50, 52, 52, 52, 52,
                                   52, 52, 52, 52, 52, 52, 52, 52};

    const dim3 blk(256);
    const dim3 gR(B_DIM / 128, M_DIM / 128);   // (128, 2)
    const dim3 gV(B_DIM / 128, N_DIM / 128);   // (128, 8)

    // ---- iteration 0: u = 0  =>  v = x @ W0^T ----
    gemm_nt<2><<<gV, blk>>>(x, W, nullptr, vp, M_DIM, N_DIM);
    select_shrink<<<B_DIM, blk>>>(vp, up, thr, 0, KTH[0]);

    // ---- iterations 1..15 ----
    for (int i = 1; i < DEPTH; ++i) {
        // r = x - u @ A^T
        gemm_nt<0><<<gR, blk>>>(up, A, x, rp, N_DIM, M_DIM);
        // v = u + r @ W[i]^T
        gemm_nt<1><<<gV, blk>>>(rp, W + (size_t)i * N_DIM * M_DIM, up, vp,
                                M_DIM, N_DIM);
        // u = shrinkss(v); last iteration writes straight to d_out
        select_shrink<<<B_DIM, blk>>>(vp, (i == DEPTH - 1) ? uout : up,
                                      thr, i, KTH[i]);
    }
}

// round 14
// speedup vs baseline: 1.0303x; 1.0303x over previous
#include <cuda_runtime.h>
#include <cstdint>
#include <cstddef>

// LISTA-CPSS: B=16384, M=256, N=1024, DEPTH=16
// Exact fp32 SIMT GEMM: 32x64 warp tiles, aligned single-wavefront LDS.128,
// BK=16, single-buffer two-barrier staging (R11 structure), MANUAL k-level
// software pipeline of smem fragments. + 2-phase bit-exact radix select.

#define B_DIM  16384
#define M_DIM  256
#define N_DIM  1024
#define DEPTH  16

__device__ float g_r[(size_t)B_DIM * M_DIM];
__device__ float g_v[(size_t)B_DIM * N_DIM];
__device__ float g_u[(size_t)B_DIM * N_DIM];

// ---------------------------------------------------------------------------
// Tiled SGEMM: C[i,j] = epilogue( sum_k X[i,k]*Y[j,k] );  X:[I,K], Y:[J,K].
// MODE 0: C = bias - acc ; MODE 1: C = bias + acc ; MODE 2: C = acc
// 128x128 CTA tile, BK=16, 256 threads, warp tile 32x64, lane tile 8x8.
// Fragment loads for k+1 issue before the FMA block for k (software pipeline)
// so each LDS has ~32 issue-cycles of latency slack.
// Per-element k-order identical to R2/R10/R11 kernels (bit-exact result).
// ---------------------------------------------------------------------------
template <int MODE>
__global__ void __launch_bounds__(256, 2)
gemm_nt(const float* __restrict__ X, const float* __restrict__ Y,
        const float* __restrict__ bias, float* __restrict__ C,
        int K, int ldc)
{
    __shared__ float sX[16][128];
    __shared__ float sY[16][128];

    const int bi  = blockIdx.x;
    const int bj  = blockIdx.y;
    const int tid = threadIdx.x;

    // ---- global -> smem loader mapping ----
    const int loadRow = tid >> 1;          // 0..127
    const int kBase   = (tid & 1) * 8;     // 0 or 8

    const float* xg = X + (size_t)(bi * 128 + loadRow) * K + kBase;
    const float* yg = Y + (size_t)(bj * 128 + loadRow) * K + kBase;

    // ---- compute mapping: warp tile 32x64, lane tile 8x8 ----
    const int lane = tid & 31;
    const int warp = tid >> 5;
    const int wy = warp & 3;
    const int wx = warp >> 2;
    const int ty = lane >> 3;
    const int tx = lane & 7;

    const int r0 = wy * 32 + ty * 4;
    const int r1 = r0 + 16;
    const int c0 = wx * 64 + tx * 4;
    const int c1 = c0 + 32;

    float acc[8][8];
#pragma unroll
    for (int p = 0; p < 8; ++p)
#pragma unroll
        for (int q = 0; q < 8; ++q) acc[p][q] = 0.0f;

    const int nch = K >> 4;   // chunks of 16

    float4 xv0 = *reinterpret_cast<const float4*>(xg);
    float4 xv1 = *reinterpret_cast<const float4*>(xg + 4);
    float4 yv0 = *reinterpret_cast<const float4*>(yg);
    float4 yv1 = *reinterpret_cast<const float4*>(yg + 4);

#pragma unroll 1
    for (int ch = 0; ch < nch; ++ch) {
        __syncthreads();
        {
            const float xa[8] = {xv0.x, xv0.y, xv0.z, xv0.w, xv1.x, xv1.y, xv1.z, xv1.w};
            const float ya[8] = {yv0.x, yv0.y, yv0.z, yv0.w, yv1.x, yv1.y, yv1.z, yv1.w};
#pragma unroll
            for (int i = 0; i < 8; ++i) {
                sX[kBase + i][loadRow] = xa[i];
                sY[kBase + i][loadRow] = ya[i];
            }
        }
        __syncthreads();

        if (ch + 1 < nch) {
            const float* xn = xg + (ch + 1) * 16;
            const float* yn = yg + (ch + 1) * 16;
            xv0 = *reinterpret_cast<const float4*>(xn);
            xv1 = *reinterpret_cast<const float4*>(xn + 4);
            yv0 = *reinterpret_cast<const float4*>(yn);
            yv1 = *reinterpret_cast<const float4*>(yn + 4);
        }

        // ---- software-pipelined fragment loop over k ----
        float4 a0c = *reinterpret_cast<const float4*>(&sX[0][r0]);
        float4 a1c = *reinterpret_cast<const float4*>(&sX[0][r1]);
        float4 b0c = *reinterpret_cast<const float4*>(&sY[0][c0]);
        float4 b1c = *reinterpret_cast<const float4*>(&sY[0][c1]);
#pragma unroll
        for (int k = 0; k < 16; ++k) {
            float4 a0n, a1n, b0n, b1n;
            if (k < 15) {
                a0n = *reinterpret_cast<const float4*>(&sX[k + 1][r0]);
                a1n = *reinterpret_cast<const float4*>(&sX[k + 1][r1]);
                b0n = *reinterpret_cast<const float4*>(&sY[k + 1][c0]);
                b1n = *reinterpret_cast<const float4*>(&sY[k + 1][c1]);
            }
            const float a[8] = {a0c.x, a0c.y, a0c.z, a0c.w, a1c.x, a1c.y, a1c.z, a1c.w};
            const float b[8] = {b0c.x, b0c.y, b0c.z, b0c.w, b1c.x, b1c.y, b1c.z, b1c.w};
#pragma unroll
            for (int p = 0; p < 8; ++p)
#pragma unroll
                for (int q = 0; q < 8; ++q) acc[p][q] += a[p] * b[q];
            if (k < 15) { a0c = a0n; a1c = a1n; b0c = b0n; b1c = b1n; }
        }
    }

    // ---- epilogue ----
    const int gr0 = bi * 128;
    const int gc0 = bj * 128;
#pragma unroll
    for (int p = 0; p < 8; ++p) {
        const int rr = gr0 + ((p < 4) ? (r0 + p) : (r1 + p - 4));
#pragma unroll
        for (int half = 0; half < 2; ++half) {
            const int cc = gc0 + ((half == 0) ? c0 : c1);
            const size_t base = (size_t)rr * ldc + cc;
            float4 o;
            float* po = reinterpret_cast<float*>(&o);
#pragma unroll
            for (int q = 0; q < 4; ++q) {
                float v = acc[p][half * 4 + q];
                if (MODE == 0)      v = bias[base + q] - v;
                else if (MODE == 1) v = bias[base + q] + v;
                po[q] = v;
            }
            *reinterpret_cast<float4*>(C + base) = o;
        }
    }
}

// ---------------------------------------------------------------------------
// select_shrink: bit-exact k-th largest |v| per row, 2-phase:
//   Phase A: 1024-bin histogram over top-11 bits + block suffix-scan.
//   Phase B: boundary-bin candidates, 3 radix passes over the small list.
// Then masked soft-threshold.
// ---------------------------------------------------------------------------
__global__ void __launch_bounds__(256)
select_shrink(const float* __restrict__ V, float* __restrict__ U,
              const float* __restrict__ thr, int iter, int kth)
{
    __shared__ unsigned s_hist[1024];
    __shared__ unsigned s_cand[1024];
    __shared__ unsigned s_wtot[8];
    __shared__ unsigned s_wabove[8];
    __shared__ unsigned s_sel[2];
    __shared__ unsigned s_cnt;

    const int row  = blockIdx.x;
    const int tid  = threadIdx.x;
    const int lane = tid & 31;
    const int wrp  = tid >> 5;

    const float4 vv = reinterpret_cast<const float4*>(V + (size_t)row * N_DIM)[tid];
    float va[4] = {vv.x, vv.y, vv.z, vv.w};
    unsigned key[4];
#pragma unroll
    for (int e = 0; e < 4; ++e) key[e] = __float_as_uint(fabsf(va[e]));

    // ---- Phase A ----
#pragma unroll
    for (int i = 0; i < 4; ++i) s_hist[tid * 4 + i] = 0;
    __syncthreads();
#pragma unroll
    for (int e = 0; e < 4; ++e) atomicAdd(&s_hist[key[e] >> 21], 1u);
    __syncthreads();

    unsigned h[4], ls[4];
#pragma unroll
    for (int i = 0; i < 4; ++i) h[i] = s_hist[tid * 4 + i];
    ls[3] = h[3];
#pragma unroll
    for (int i = 2; i >= 0; --i) ls[i] = h[i] + ls[i + 1];
    const unsigned tot = ls[0];

    unsigned suf = tot;
#pragma unroll
    for (int d = 1; d < 32; d <<= 1) {
        const unsigned t = __shfl_down_sync(0xFFFFFFFFu, suf, d);
        if (lane + d < 32) suf += t;
    }
    if (lane == 0) s_wtot[wrp] = suf;
    __syncthreads();
    if (tid == 0) {
        unsigned run = 0;
        for (int w = 7; w >= 0; --w) { s_wabove[w] = run; run += s_wtot[w]; }
    }
    __syncthreads();

    {
        const unsigned A = s_wabove[wrp] + (suf - tot);
        const unsigned k = (unsigned)kth;
#pragma unroll
        for (int i = 0; i < 4; ++i) {
            const unsigned sb = A + ls[i];
            const unsigned sn = (i < 3) ? (A + ls[i + 1]) : A;
            if (sb >= k && sn < k) {
                s_sel[0] = (unsigned)(tid * 4 + i);
                s_sel[1] = k - sn;
            }
        }
    }
    __syncthreads();
    const unsigned selbin = s_sel[0];
    unsigned rem          = s_sel[1];

    // ---- Phase B ----
    if (tid == 0) s_cnt = 0;
    __syncthreads();
#pragma unroll
    for (int e = 0; e < 4; ++e) {
        if ((key[e] >> 21) == selbin) {
            const unsigned idx = atomicAdd(&s_cnt, 1u);
            s_cand[idx] = key[e];
        }
    }
    __syncthreads();
    const unsigned c = s_cnt;

    unsigned prefix = selbin << 21;
    const int SHIFT[3] = {13, 5, 0};
    const unsigned HIMASK[3] = {0xFFE00000u, 0xFFFFE000u, 0xFFFFFFE0u};
    const unsigned BMASK[3]  = {255u, 255u, 31u};

#pragma unroll 1
    for (int pass = 0; pass < 3; ++pass) {
        if (tid < 256) s_hist[tid] = 0;
        __syncthreads();
        for (unsigned j = tid; j < c; j += 256) {
            const unsigned kk = s_cand[j];
            if ((kk & HIMASK[pass]) == prefix)
                atomicAdd(&s_hist[(kk >> SHIFT[pass]) & BMASK[pass]], 1u);
        }
        __syncthreads();

        if (tid < 32) {
            unsigned v8[8], l8[8];
#pragma unroll
            for (int i = 0; i < 8; ++i) v8[i] = s_hist[tid * 8 + i];
            l8[7] = v8[7];
#pragma unroll
            for (int i = 6; i >= 0; --i) l8[i] = v8[i] + l8[i + 1];
            const unsigned t8 = l8[0];
            unsigned sf = t8;
#pragma unroll
            for (int d = 1; d < 32; d <<= 1) {
                const unsigned t = __shfl_down_sync(0xFFFFFFFFu, sf, d);
                if (tid + d < 32) sf += t;
            }
            const unsigned above = sf - t8;
#pragma unroll
            for (int i = 0; i < 8; ++i) {
                const unsigned sb = above + l8[i];
                const unsigned sn = above + ((i < 7) ? l8[i + 1] : 0u);
                if (sb >= rem && sn < rem) {
                    s_sel[0] = (unsigned)(tid * 8 + i);
                    s_sel[1] = rem - sn;
                }
            }
        }
        __syncthreads();
        prefix |= s_sel[0] << SHIFT[pass];
        rem     = s_sel[1];
        __syncthreads();
    }

    const float th = __uint_as_float(prefix);
    const float t  = thr[iter];

    float4 ov;
    float* po = reinterpret_cast<float*>(&ov);
#pragma unroll
    for (int e = 0; e < 4; ++e) {
        const float x = va[e];
        const float a = fabsf(x);
        po[e] = (a >= t && a >= th) ? x : copysignf(fmaxf(a - t, 0.0f), x);
    }
    reinterpret_cast<float4*>(U + (size_t)row * N_DIM)[tid] = ov;
}

// ---------------------------------------------------------------------------
extern "C" void kernel_launch(void* const* d_in, const int* in_sizes, int n_in,
                              void* d_out, int out_size)
{
    const float* x   = (const float*)d_in[0];   // [B, M]
    const float* A   = (const float*)d_in[1];   // [M, N]
    const float* W   = (const float*)d_in[2];   // [DEPTH, N, M]
    const float* thr = (const float*)d_in[3];   // [DEPTH]
    float* uout = (float*)d_out;                // [B, N]

    float *rp, *vp, *up;
    cudaGetSymbolAddress((void**)&rp, g_r);
    cudaGetSymbolAddress((void**)&vp, g_v);
    cudaGetSymbolAddress((void**)&up, g_u);

    // kth_i = 1024 - (ceil((100 - p_i)/100 * 1024) - 1), p_i = min((i+1)*1.2, 5)
    static const int KTH[DEPTH] = {13, 25, 37, 50, 52, 52, 52, 52,
                                   52, 52, 52, 52, 52, 52, 52, 52};

    const dim3 blk(256);
    const dim3 gR(B_DIM / 128, M_DIM / 128);   // (128, 2)
    const dim3 gV(B_DIM / 128, N_DIM / 128);   // (128, 8)

    // ---- iteration 0: u = 0  =>  v = x @ W0^T ----
    gemm_nt<2><<<gV, blk>>>(x, W, nullptr, vp, M_DIM, N_DIM);
    select_shrink<<<B_DIM, blk>>>(vp, up, thr, 0, KTH[0]);

    // ---- iterations 1..15 ----
    for (int i = 1; i < DEPTH; ++i) {
        // r = x - u @ A^T
        gemm_nt<0><<<gR, blk>>>(up, A, x, rp, N_DIM, M_DIM);
        // v = u + r @ W[i]^T
        gemm_nt<1><<<gV, blk>>>(rp, W + (size_t)i * N_DIM * M_DIM, up, vp,
                                M_DIM, N_DIM);
        // u = shrinkss(v); last iteration writes straight to d_out
        select_shrink<<<B_DIM, blk>>>(vp, (i == DEPTH - 1) ? uout : up,
                                      thr, i, KTH[i]);
    }
}